// round 1
// baseline (speedup 1.0000x reference)
#include <cuda_runtime.h>

// Chunk-local reverse inclusive cumsum with scale fusion.
//   g: [B, T, H] f32, BT=64 chunks along T, H=64.
//   out[b, c, t, h] = SCALE * sum_{s >= t} g[b, c, s, h]
//
// Mapping: one thread per (chunk, h-quad). Each thread walks t = BT-1 .. 0,
// accumulating 4 suffix sums in registers (float4), fully coalesced
// LDG.128/STG.128 per warp. Pure streaming kernel: read once, write once.

static constexpr int BT = 64;
static constexpr int H  = 64;
static constexpr int HQ = H / 4;          // float4 quads per row = 16
static constexpr float SCALE = 0.5f;

__global__ __launch_bounds__(256, 8)
void rev_cumsum_kernel(const float4* __restrict__ g,
                       float4* __restrict__ out,
                       int n_cols)  // total (chunk, h-quad) columns
{
    int tid = blockIdx.x * blockDim.x + threadIdx.x;
    if (tid >= n_cols) return;

    int hq    = tid & (HQ - 1);           // 0..15
    int chunk = tid >> 4;                 // global chunk index

    // base index (in float4 units) of row t=0 of this chunk, at this h-quad
    long long base = (long long)chunk * (BT * HQ) + hq;

    float4 run = make_float4(0.f, 0.f, 0.f, 0.f);

    #pragma unroll
    for (int t = BT - 1; t >= 0; --t) {
        float4 v = g[base + (long long)t * HQ];
        run.x += v.x;
        run.y += v.y;
        run.z += v.z;
        run.w += v.w;
        float4 o;
        o.x = run.x * SCALE;
        o.y = run.y * SCALE;
        o.z = run.z * SCALE;
        o.w = run.w * SCALE;
        out[base + (long long)t * HQ] = o;
    }
}

extern "C" void kernel_launch(void* const* d_in, const int* in_sizes, int n_in,
                              void* d_out, int out_size)
{
    const float4* g   = (const float4*)d_in[0];
    float4*       out = (float4*)d_out;

    int total_elems = in_sizes[0];            // B * T * H
    int n_cols = total_elems / (BT * H) * HQ; // chunks * h-quads

    int threads = 256;
    int blocks  = (n_cols + threads - 1) / threads;
    rev_cumsum_kernel<<<blocks, threads>>>(g, out, n_cols);
}